// round 9
// baseline (speedup 1.0000x reference)
#include <cuda_runtime.h>
#include <cuda_bf16.h>

// out[g, :] = sum over rows r with batch[r]==g of x[r, :]
// (softmax over a size-1 axis == 1.0 -> W, b mathematically dead).
// x: [N, 128] fp32, batch: [N] int32 SORTED, out: [10000, 128] fp32.
//
// Inputs identified BY ELEMENT COUNT (robust to metadata ordering).
//
// R8 core (75% DRAM, regs 32) + PERSISTENT GRID with dynamic chunk stealing:
// grid = SMs x 8 blocks (exactly one wave at the regs=32 occupancy limit).
// Each warp atomically grabs the next 64-row chunk until all are consumed —
// no wave-quantization tail, auto-balances SM/die speed variance.
// Per-chunk: register run-length accumulate over sorted ids, flush via
// red.global.add.v4.f32 at segment boundaries. x loads are __ldcs streaming.

#define C            128
#define TX           32
#define TY           8
#define ROWS_PER_CHUNK 64

__device__ int g_chunk_counter;

__device__ __forceinline__ void red_add_v4(float* addr, float4 v) {
    asm volatile("red.global.add.v4.f32 [%0], {%1, %2, %3, %4};"
                 :: "l"(addr), "f"(v.x), "f"(v.y), "f"(v.z), "f"(v.w)
                 : "memory");
}

__global__ __launch_bounds__(TX * TY, 8)
void segsum_kernel(const float4* __restrict__ x4,     // [N, 32] float4 view
                   const int* __restrict__ batch,     // [N] int32 sorted
                   float* __restrict__ out,           // [G, 128]
                   int N, int G, int numChunks) {
    const int tx = threadIdx.x;      // 0..31 -> column group (float4)

    for (;;) {
        int c;
        if (tx == 0) c = atomicAdd(&g_chunk_counter, 1);
        c = __shfl_sync(0xffffffffu, c, 0);
        if (c >= numChunks) break;

        int r0 = c * ROWS_PER_CHUNK;
        int rend = min(r0 + ROWS_PER_CHUNK, N);

        float4 acc = make_float4(0.f, 0.f, 0.f, 0.f);
        int cur = __ldg(&batch[r0]);    // uniform -> broadcast

        #pragma unroll 4
        for (int r = r0; r < rend; ++r) {
            int b = __ldg(&batch[r]);               // uniform broadcast load
            float4 v = __ldcs(&x4[(size_t)r * (C / 4) + tx]);  // streaming
            if (b != cur) {
                int g = min(max(cur, 0), G - 1);    // defensive clamp
                red_add_v4(out + (size_t)g * C + tx * 4, acc);
                acc = make_float4(0.f, 0.f, 0.f, 0.f);
                cur = b;
            }
            acc.x += v.x; acc.y += v.y; acc.z += v.z; acc.w += v.w;
        }
        int g = min(max(cur, 0), G - 1);
        red_add_v4(out + (size_t)g * C + tx * 4, acc);
    }
}

extern "C" void kernel_launch(void* const* d_in, const int* in_sizes, int n_in,
                              void* d_out, int out_size) {
    // --- identify inputs by element count (robust to metadata ordering) ---
    int xi = 0;
    long long best = -1;
    for (int i = 0; i < n_in; ++i)
        if ((long long)in_sizes[i] > best) { best = in_sizes[i]; xi = i; }
    const int N = in_sizes[xi] / C;
    int bi = -1;
    for (int i = 0; i < n_in; ++i)
        if (i != xi && in_sizes[i] == N) { bi = i; break; }
    if (bi < 0) bi = (xi == 1) ? 0 : 1;

    const float* x     = (const float*)d_in[xi];
    const int*   batch = (const int*)d_in[bi];
    float* out = (float*)d_out;
    const int G = out_size / C;
    const int numChunks = (N + ROWS_PER_CHUNK - 1) / ROWS_PER_CHUNK;

    // Reset the work-stealing counter (graph-capturable memset node).
    static void* counter_addr = nullptr;
    if (!counter_addr) cudaGetSymbolAddress(&counter_addr, g_chunk_counter);
    cudaMemsetAsync(counter_addr, 0, sizeof(int));

    // Zero the poisoned output (atomics accumulate into it).
    cudaMemsetAsync(out, 0, (size_t)out_size * sizeof(float));

    // Persistent grid: one full wave at the regs<=32 / 8-blocks-per-SM limit.
    static int smCount = 0;
    if (smCount == 0) {
        if (cudaDeviceGetAttribute(&smCount, cudaDevAttrMultiProcessorCount, 0)
                != cudaSuccess || smCount <= 0)
            smCount = 148;
    }
    dim3 block(TX, TY);
    int grid = smCount * 8;
    segsum_kernel<<<grid, block>>>((const float4*)x, batch, out, N, G, numChunks);
}

// round 10
// speedup vs baseline: 1.1887x; 1.1887x over previous
#include <cuda_runtime.h>
#include <cuda_bf16.h>

// out[g, :] = sum over rows r with batch[r]==g of x[r, :]
// (softmax over a size-1 axis == 1.0 -> W, b mathematically dead).
// x: [N, 128] fp32, batch: [N] int32 SORTED, out: [10000, 128] fp32.
//
// Inputs identified BY ELEMENT COUNT (robust to metadata ordering).
//
// R8 core (best: 75% DRAM, regs 32, static contiguous per-warp rows,
// __ldcs streams, red.global.add.v4.f32 flushes, memset prologue) with ONE
// change: grid sized to EXACTLY 2.0 waves at the regs=32 residency limit
// (148 SMs x 8 blocks resident -> grid 2368), rows-per-warp = ceil(N/18944).
// Eliminates the 0.65-partial-wave tail of R8 without any dynamic stealing
// (R9 showed atomics' serial chunk-head latency kills outstanding-load count).

#define C    128
#define TX   32
#define TY   8
#define BLOCKS_PER_SM 8

__device__ __forceinline__ void red_add_v4(float* addr, float4 v) {
    asm volatile("red.global.add.v4.f32 [%0], {%1, %2, %3, %4};"
                 :: "l"(addr), "f"(v.x), "f"(v.y), "f"(v.z), "f"(v.w)
                 : "memory");
}

__global__ __launch_bounds__(TX * TY, BLOCKS_PER_SM)
void segsum_kernel(const float4* __restrict__ x4,     // [N, 32] float4 view
                   const int* __restrict__ batch,     // [N] int32 sorted
                   float* __restrict__ out,           // [G, 128]
                   int N, int G, int rowsPerWarp) {
    const int tx = threadIdx.x;                       // column group
    const int wid = blockIdx.x * TY + threadIdx.y;    // flat warp id

    int r0 = wid * rowsPerWarp;
    if (r0 >= N) return;
    int rend = min(r0 + rowsPerWarp, N);

    float4 acc = make_float4(0.f, 0.f, 0.f, 0.f);
    int cur = __ldg(&batch[r0]);        // uniform across warp -> broadcast

    #pragma unroll 4
    for (int r = r0; r < rend; ++r) {
        int b = __ldg(&batch[r]);               // uniform broadcast load
        float4 v = __ldcs(&x4[(size_t)r * (C / 4) + tx]);  // streaming load
        if (b != cur) {
            int g = min(max(cur, 0), G - 1);    // defensive clamp
            red_add_v4(out + (size_t)g * C + tx * 4, acc);
            acc = make_float4(0.f, 0.f, 0.f, 0.f);
            cur = b;
        }
        acc.x += v.x; acc.y += v.y; acc.z += v.z; acc.w += v.w;
    }
    int g = min(max(cur, 0), G - 1);
    red_add_v4(out + (size_t)g * C + tx * 4, acc);
}

extern "C" void kernel_launch(void* const* d_in, const int* in_sizes, int n_in,
                              void* d_out, int out_size) {
    // --- identify inputs by element count (robust to metadata ordering) ---
    int xi = 0;
    long long best = -1;
    for (int i = 0; i < n_in; ++i)
        if ((long long)in_sizes[i] > best) { best = in_sizes[i]; xi = i; }
    const int N = in_sizes[xi] / C;
    int bi = -1;
    for (int i = 0; i < n_in; ++i)
        if (i != xi && in_sizes[i] == N) { bi = i; break; }
    if (bi < 0) bi = (xi == 1) ? 0 : 1;

    const float* x     = (const float*)d_in[xi];
    const int*   batch = (const int*)d_in[bi];
    float* out = (float*)d_out;
    const int G = out_size / C;

    // Zero the poisoned output (atomics accumulate into it).
    cudaMemsetAsync(out, 0, (size_t)out_size * sizeof(float));

    // Exactly 2.0 waves at the regs=32 residency limit.
    static int smCount = 0;
    if (smCount == 0) {
        if (cudaDeviceGetAttribute(&smCount, cudaDevAttrMultiProcessorCount, 0)
                != cudaSuccess || smCount <= 0)
            smCount = 148;
    }
    const int grid = smCount * BLOCKS_PER_SM * 2;        // 2368 on 148 SMs
    const int totalWarps = grid * TY;
    const int rowsPerWarp = (N + totalWarps - 1) / totalWarps;   // 53 for 1e6

    dim3 block(TX, TY);
    segsum_kernel<<<grid, block>>>((const float4*)x, batch, out,
                                   N, G, rowsPerWarp);
}